// round 13
// baseline (speedup 1.0000x reference)
#include <cuda_runtime.h>
#include <cuda_fp16.h>
#include <math.h>

// Problem constants (fixed by the reference).
#define CC 128      // channels
#define WW 8        // hidden width
#define BB 8        // batch
#define TT 16000    // time

// LUT parameters
#define NTAB 4096                 // segments; 4B/entry -> 16 KB smem
#define XLO (-9.0f)
#define XHI (9.0f)

#define TPB 256                   // threads per block (main kernel)
#define BSEGS 16                  // build: 256 threads x 16 segs = 4096

// Per-channel PWL tables: entry i = half2{slope_i, y0_i} with
//   F(x) ~= y0_i + slope_i * (u - i),  u = (x - XLO) * NTAB/(XHI-XLO)
__device__ __half2 g_tab[CC * NTAB];

// ---------------- fast per-channel MLP (table build only) -----------------
__device__ __forceinline__ float ex2a(float a) {
    float e;
    asm("ex2.approx.f32 %0, %1;" : "=f"(e) : "f"(a));
    return e;
}
#define LOG2E 1.44269504088896340736f

__device__ __forceinline__ float elu_f(float y) {
    float e = ex2a(y * LOG2E) - 1.0f;
    return y > 0.0f ? y : e;
}

__device__ __forceinline__ float mlp_eval_r(float xg,
                                            const float* rw1, const float* rb1,
                                            const float* rw2, const float* rb2,
                                            const float* rw3, float rb3) {
    float h1[WW], h2[WW];
#pragma unroll
    for (int v = 0; v < WW; v++)
        h1[v] = elu_f(fmaf(rw1[v], xg, rb1[v]));
#pragma unroll
    for (int v = 0; v < WW; v++) {
        float a = rb2[v];
#pragma unroll
        for (int w = 0; w < WW; w++)
            a = fmaf(rw2[v * WW + w], h1[w], a);
        h2[v] = elu_f(a);
    }
    float a = rb3;
#pragma unroll
    for (int v = 0; v < WW; v++)
        a = fmaf(rw3[v], h2[v], a);
    return elu_f(a);
}

// Fused build: one block per channel; each thread loads the 97 channel weights
// into registers ONCE and streams 17 grid evals -> 16 half2 entries.
__global__ void __launch_bounds__(NTAB / BSEGS)
build_kernel(const float* __restrict__ w1, const float* __restrict__ b1,
             const float* __restrict__ w2, const float* __restrict__ b2,
             const float* __restrict__ w3, const float* __restrict__ b3) {
    const int c  = blockIdx.x;
    const int s0 = threadIdx.x * BSEGS;               // first segment

    float rw1[WW], rb1[WW], rw2[WW * WW], rb2[WW], rw3[WW];
#pragma unroll
    for (int v = 0; v < WW; v++) {
        rw1[v] = __ldg(w1 + c * WW + v);
        rb1[v] = __ldg(b1 + c * WW + v);
        rb2[v] = __ldg(b2 + c * WW + v);
        rw3[v] = __ldg(w3 + c * WW + v);
    }
#pragma unroll
    for (int k = 0; k < WW * WW; k++)
        rw2[k] = __ldg(w2 + c * WW * WW + k);
    const float rb3 = __ldg(b3 + c);

    const float H = (XHI - XLO) / (float)NTAB;
    __half2* ot = g_tab + (size_t)c * NTAB + s0;

    float yprev = mlp_eval_r(XLO + (float)s0 * H, rw1, rb1, rw2, rb2, rw3, rb3);
#pragma unroll
    for (int k = 1; k <= BSEGS; k++) {
        float ycur = mlp_eval_r(XLO + (float)(s0 + k) * H,
                                rw1, rb1, rw2, rb2, rw3, rb3);
        float s = ycur - yprev;
        ot[k - 1] = __halves2half2(__float2half_rn(s), __float2half_rn(yprev));
        yprev = ycur;
    }
}

// ---------------- main streaming kernel -----------------------------------
__device__ __forceinline__ float lut1(float xv, const __half2* __restrict__ stab,
                                      float invH, float uoff, float umax) {
    float u = fmaf(xv, invH, uoff);
    u = fminf(fmaxf(u, 0.0f), umax);
    int i = (int)u;                    // u >= 0 -> trunc == floor
    float fi = (float)i;
    float2 sc = __half22float2(stab[i]);   // LDS.32: {slope, y0}
    return fmaf(sc.x, u - fi, sc.y);
}

__global__ void __launch_bounds__(TPB)
tnl_kernel(const float* __restrict__ x, float* __restrict__ out) {
    __shared__ __half2 stab[NTAB];     // 16 KB

    const int row = blockIdx.x;        // row = b*CC + c, one full row per block
    const int c   = row & (CC - 1);

    // copy this channel's table into smem (1024 float4s)
    {
        const float4* src = (const float4*)(g_tab + (size_t)c * NTAB);
        float4* dst = (float4*)stab;
#pragma unroll
        for (int k = threadIdx.x; k < NTAB / 4; k += TPB)
            dst[k] = __ldg(src + k);
    }
    __syncthreads();

    const float invH = (float)NTAB / (XHI - XLO);
    const float uoff = -XLO * invH;
    const float umax = (float)NTAB - 0.001f;

    const size_t base = (size_t)row * TT;
    const float4* __restrict__ xin  = (const float4*)(x + base);
    float4* __restrict__       oout = (float4*)(out + base);
    const int n4 = TT / 4;             // 4000

#pragma unroll 2
    for (int i = threadIdx.x; i < n4; i += TPB) {
        float4 v = __ldcs(xin + i);    // streaming read (touched once)
        float4 r;
        r.x = lut1(v.x, stab, invH, uoff, umax);
        r.y = lut1(v.y, stab, invH, uoff, umax);
        r.z = lut1(v.z, stab, invH, uoff, umax);
        r.w = lut1(v.w, stab, invH, uoff, umax);
        __stcs(oout + i, r);           // streaming write
    }
}

extern "C" void kernel_launch(void* const* d_in, const int* in_sizes, int n_in,
                              void* d_out, int out_size) {
    const float* x  = (const float*)d_in[0];
    const float* w1 = (const float*)d_in[1];
    const float* b1 = (const float*)d_in[2];
    const float* w2 = (const float*)d_in[3];
    const float* b2 = (const float*)d_in[4];
    const float* w3 = (const float*)d_in[5];
    const float* b3 = (const float*)d_in[6];
    float* out = (float*)d_out;

    build_kernel<<<CC, NTAB / BSEGS>>>(w1, b1, w2, b2, w3, b3);
    tnl_kernel<<<BB * CC, TPB>>>(x, out);
}